// round 6
// baseline (speedup 1.0000x reference)
#include <cuda_runtime.h>
#include <math.h>

#define NRAYS 16384
#define MAXS 128

typedef unsigned long long u64;

// ---------------- scratch (device globals; no allocation allowed) ----------
__device__ float g_dirs[NRAYS * 3];
__device__ float g_dbuf[2][NRAYS * MAXS];
__device__ float g_sbuf[2][NRAYS * MAXS];
__device__ float g_dfine[NRAYS * 16];
__device__ float g_sdff[NRAYS * 16];

// ---------------- math helpers ---------------------------------------------
__device__ __forceinline__ float softplus_fast(float x) {
    float t = __expf(-fabsf(x));
    return fmaxf(x, 0.0f) + __logf(1.0f + t);
}
__device__ __forceinline__ float sigmoid_fast(float x) {
    return __fdividef(1.0f, 1.0f + __expf(-x));
}
__device__ __forceinline__ float sigmoid_precise(float x) {
    return 1.0f / (1.0f + expf(-x));
}

// ---------------- packed f32x2 helpers (Blackwell FFMA2) --------------------
__device__ __forceinline__ u64 pack2(float lo, float hi) {
    u64 r;
    asm("mov.b64 %0, {%1, %2};" : "=l"(r) : "f"(lo), "f"(hi));
    return r;
}
__device__ __forceinline__ void unpack2(u64 v, float& lo, float& hi) {
    asm("mov.b64 {%0, %1}, %2;" : "=f"(lo), "=f"(hi) : "l"(v));
}
__device__ __forceinline__ u64 ffma2(u64 a, u64 b, u64 c) {
    u64 d;
    asm("fma.rn.f32x2 %0, %1, %2, %3;" : "=l"(d) : "l"(a), "l"(b), "l"(c));
    return d;
}
__device__ __forceinline__ u64 fadd2(u64 a, u64 b) {
    u64 d;
    asm("add.rn.f32x2 %0, %1, %2;" : "=l"(d) : "l"(a), "l"(b));
    return d;
}

// ---------------- init: normalize dirs, fill coarse d ----------------------
__global__ void init_kernel(const float* __restrict__ rd,
                            const float* __restrict__ nearp,
                            const float* __restrict__ farp) {
    int r = blockIdx.x * blockDim.x + threadIdx.x;
    if (r >= NRAYS) return;
    float dx = rd[r * 3 + 0], dy = rd[r * 3 + 1], dz = rd[r * 3 + 2];
    float nrm = sqrtf(dx * dx + dy * dy + dz * dz);
    dx /= nrm; dy /= nrm; dz /= nrm;
    g_dirs[r * 3 + 0] = dx; g_dirs[r * 3 + 1] = dy; g_dirs[r * 3 + 2] = dz;
    float nr = nearp[r], fr = farp[r];
    for (int j = 0; j < 64; j++) {
        float t = (float)j / 63.0f;
        g_dbuf[0][r * MAXS + j] = nr * (1.0f - t) + fr * t;
    }
}

// ---------------- SDF MLP eval: 2 points/thread, f32x2 packed layer-2 -------
// mode 0: coarse (g_dbuf[0], stride 128, 64/ray -> g_sbuf[0])
// mode 1: fine   (g_dfine, stride 16, 16/ray -> g_sdff)
__global__ void __launch_bounds__(256)
sdf_kernel(const float* __restrict__ o,
           const float* __restrict__ w1, const float* __restrict__ b1,
           const float* __restrict__ w2, const float* __restrict__ b2,
           const float* __restrict__ w3, const float* __restrict__ b3,
           int mode, int npts) {
    __shared__ __align__(16) float w2t[64 * 64];  // w2t[j*64+k] = w2[k*64+j]
    __shared__ float w1s[192], b1s[64], b2s[64], w3s[64];
    __shared__ float b3s;

    int tid = threadIdx.x;
    for (int i = tid; i < 4096; i += blockDim.x) {
        w2t[(i & 63) * 64 + (i >> 6)] = w2[i];
    }
    for (int i = tid; i < 192; i += blockDim.x) w1s[i] = w1[i];
    if (tid < 64) { b1s[tid] = b1[tid]; b2s[tid] = b2[tid]; w3s[tid] = w3[tid]; }
    if (tid == 0) b3s = b3[0];
    __syncthreads();

    int p0 = 2 * (blockIdx.x * blockDim.x + tid);
    if (p0 >= npts) return;

    const float* dvals = mode ? g_dfine : g_dbuf[0];
    float* outp        = mode ? g_sdff  : g_sbuf[0];
    int spr    = mode ? 16 : 64;
    int stride = mode ? 16 : MAXS;

    // p0 even, spr even -> p0 and p0+1 always share a ray
    int ray = p0 / spr;
    int j0  = p0 - ray * spr;
    float dv0 = dvals[ray * stride + j0];
    float dv1 = dvals[ray * stride + j0 + 1];

    float ox = o[ray * 3 + 0], oy = o[ray * 3 + 1], oz = o[ray * 3 + 2];
    float dx = g_dirs[ray * 3 + 0], dy = g_dirs[ray * 3 + 1], dz = g_dirs[ray * 3 + 2];
    float pax = fmaf(dv0, dx, ox), pay = fmaf(dv0, dy, oy), paz = fmaf(dv0, dz, oz);
    float pbx = fmaf(dv1, dx, ox), pby = fmaf(dv1, dy, oy), pbz = fmaf(dv1, dz, oz);

    // layer 1: 3 -> 64 softplus; pack adjacent-q pairs per point
    u64 ha[32], hb[32];
#pragma unroll
    for (int q = 0; q < 64; q += 2) {
        float w00 = w1s[q],       w01 = w1s[q + 1];
        float w10 = w1s[64 + q],  w11 = w1s[64 + q + 1];
        float w20 = w1s[128 + q], w21 = w1s[128 + q + 1];
        float b0  = b1s[q],       bq1 = b1s[q + 1];
        float ae = fmaf(paz, w20, fmaf(pay, w10, fmaf(pax, w00, b0)));
        float ao = fmaf(paz, w21, fmaf(pay, w11, fmaf(pax, w01, bq1)));
        float be = fmaf(pbz, w20, fmaf(pby, w10, fmaf(pbx, w00, b0)));
        float bo = fmaf(pbz, w21, fmaf(pby, w11, fmaf(pbx, w01, bq1)));
        ha[q >> 1] = pack2(softplus_fast(ae), softplus_fast(ao));
        hb[q >> 1] = pack2(softplus_fast(be), softplus_fast(bo));
    }

    // layer 2: 64 -> 64 softplus, fused layer 3 (64 -> 1)
    // packed across adjacent k: (h[2k],h[2k+1]) * (w[2k],w[2k+1])
    float outa = b3s, outb = b3s;
#pragma unroll 2
    for (int q = 0; q < 64; q++) {
        const ulonglong2* wrow = (const ulonglong2*)&w2t[q * 64];
        u64 a0 = 0, a1 = 0, c0 = 0, c1 = 0;
#pragma unroll
        for (int k = 0; k < 16; k++) {
            ulonglong2 w = wrow[k];
            a0 = ffma2(ha[2 * k],     w.x, a0);
            a1 = ffma2(ha[2 * k + 1], w.y, a1);
            c0 = ffma2(hb[2 * k],     w.x, c0);
            c1 = ffma2(hb[2 * k + 1], w.y, c1);
        }
        float w3q = w3s[q], b2q = b2s[q];
        float alo, ahi, clo, chi;
        unpack2(fadd2(a0, a1), alo, ahi);
        unpack2(fadd2(c0, c1), clo, chi);
        float hva = softplus_fast(b2q + alo + ahi);
        float hvb = softplus_fast(b2q + clo + chi);
        outa = fmaf(hva, w3q, outa);
        outb = fmaf(hvb, w3q, outb);
    }

    float na = sqrtf(fmaf(pax, pax, fmaf(pay, pay, paz * paz)));
    float nb = sqrtf(fmaf(pbx, pbx, fmaf(pby, pby, pbz * pbz)));
    outp[ray * stride + j0]     = na - 0.8f + 0.1f * outa;
    outp[ray * stride + j0 + 1] = nb - 0.8f + 0.1f * outb;
}

// ---------------- upsample: one warp per ray --------------------------------
#define UP_PAD 116
__global__ void upsample_kernel(int n, float s_i, int pp) {
    int gwarp = (blockIdx.x * blockDim.x + threadIdx.x) >> 5;
    int lane  = threadIdx.x & 31;
    int wib   = (threadIdx.x >> 5);
    __shared__ float scdf[8 * UP_PAD];
    if (gwarp >= NRAYS) return;

    const float* d  = g_dbuf[pp] + gwarp * MAXS;
    const float* sd = g_sbuf[pp] + gwarp * MAXS;
    int m = n - 1;
    int base = lane * 4;

    float dj[5], sj[5];
#pragma unroll
    for (int i = 0; i < 5; i++) {
        int idx = base + i;
        bool v = idx < n;
        dj[i] = v ? d[idx] : 1.0f;
        sj[i] = v ? sd[idx] : 0.0f;
    }

    float raw[4];
#pragma unroll
    for (int i = 0; i < 4; i++)
        raw[i] = (sj[i + 1] - sj[i]) / (dj[i + 1] - dj[i] + 1e-5f);

    float prevr = __shfl_up_sync(0xffffffffu, raw[3], 1);
    if (lane == 0) prevr = 0.0f;

    float alpha[4];
#pragma unroll
    for (int i = 0; i < 4; i++) {
        float dvv = fminf(prevr, raw[i]);
        prevr = raw[i];
        dvv = fminf(fmaxf(dvv, -10.0f), 0.0f);
        float mid  = 0.5f * (sj[i] + sj[i + 1]);
        float dist = dj[i + 1] - dj[i];
        float pe = mid - dvv * dist * 0.5f;
        float ne = mid + dvv * dist * 0.5f;
        float pc = sigmoid_precise(pe * s_i);
        float nc = sigmoid_precise(ne * s_i);
        alpha[i] = (pc - nc + 1e-5f) / (pc + 1e-5f);
    }

    float Tloc[4], pl = 1.0f;
#pragma unroll
    for (int i = 0; i < 4; i++) {
        Tloc[i] = pl;
        float om = (base + i < m) ? (1.0f - alpha[i] + 1e-10f) : 1.0f;
        pl *= om;
    }
    float v = pl;
#pragma unroll
    for (int off = 1; off < 32; off <<= 1) {
        float t = __shfl_up_sync(0xffffffffu, v, off);
        if (lane >= off) v *= t;
    }
    float exp_ = __shfl_up_sync(0xffffffffu, v, 1);
    if (lane == 0) exp_ = 1.0f;

    float wp[4], sl = 0.0f, sloc[4];
#pragma unroll
    for (int i = 0; i < 4; i++) {
        float T = exp_ * Tloc[i];
        wp[i] = (base + i < m) ? fmaf(alpha[i], T, 1e-5f) : 0.0f;
        sl += wp[i];
        sloc[i] = sl;
    }
    float tot = sl;
#pragma unroll
    for (int off = 16; off > 0; off >>= 1)
        tot += __shfl_xor_sync(0xffffffffu, tot, off);
    float vs = sl;
#pragma unroll
    for (int off = 1; off < 32; off <<= 1) {
        float t = __shfl_up_sync(0xffffffffu, vs, off);
        if (lane >= off) vs += t;
    }
    float exs = __shfl_up_sync(0xffffffffu, vs, 1);
    if (lane == 0) exs = 0.0f;

    float inv = 1.0f / tot;
    float* cdf = scdf + wib * UP_PAD;
    if (lane == 0) cdf[0] = 0.0f;
#pragma unroll
    for (int i = 0; i < 4; i++) {
        int j = base + i;
        if (j < m) cdf[j + 1] = (exs + sloc[i]) * inv;
    }
    __syncwarp();

    if (lane < 16) {
        float u = (float)lane / 15.0f;
        int lo = 0, hi = n;
        while (lo < hi) {
            int mm = (lo + hi) >> 1;
            if (cdf[mm] <= u) lo = mm + 1; else hi = mm;
        }
        int below = lo - 1;
        if (below < 0) below = 0;
        if (below > n - 1) below = n - 1;
        int above = lo;
        if (above > n - 1) above = n - 1;
        float cb = cdf[below], ca = cdf[above];
        float bb = d[below],   ba = d[above];
        float den = ca - cb;
        if (den < 1e-5f) den = 1.0f;
        float t = (u - cb) / den;
        g_dfine[gwarp * 16 + lane] = bb + t * (ba - bb);
    }
}

// ---------------- parallel stable merge (rank & scatter), ping-pong ---------
__global__ void merge_kernel(int n, int pp) {
    int gwarp = (blockIdx.x * blockDim.x + threadIdx.x) >> 5;
    int lane  = threadIdx.x & 31;
    if (gwarp >= NRAYS) return;
    const float* d  = g_dbuf[pp] + gwarp * MAXS;
    const float* sd = g_sbuf[pp] + gwarp * MAXS;
    float* dd = g_dbuf[pp ^ 1] + gwarp * MAXS;
    float* ds = g_sbuf[pp ^ 1] + gwarp * MAXS;
    const float* fd = g_dfine + gwarp * 16;
    const float* fs = g_sdff  + gwarp * 16;

    if (lane < 16) {
        float v = fd[lane];
        int lo = 0, hi = n;                // count old <= v
        while (lo < hi) { int mm = (lo + hi) >> 1; if (d[mm] <= v) lo = mm + 1; else hi = mm; }
        dd[lo + lane] = v;
        ds[lo + lane] = fs[lane];
    }
    for (int a = lane; a < n; a += 32) {
        float v = d[a];
        int lo = 0, hi = 16;               // count new < v
        while (lo < hi) { int mm = (lo + hi) >> 1; if (fd[mm] < v) lo = mm + 1; else hi = mm; }
        dd[a + lo] = v;
        ds[a + lo] = sd[a];
    }
}

// ---------------- final render: compositing + radiance MLP ------------------
__global__ void render_kernel(const float* __restrict__ o,
                              const float* __restrict__ sp,
                              const float* __restrict__ w1, const float* __restrict__ b1,
                              const float* __restrict__ w2, const float* __restrict__ b2,
                              float* __restrict__ out) {
    int r = blockIdx.x;
    int tid = threadIdx.x;
    __shared__ float dsh[128], cdfsh[128], alphash[128], scan[128];
    __shared__ float w1s[384], b1s[64], w2s[192], b2s[3];
    __shared__ float red0[128], red1[128], red2[128];

    for (int i = tid; i < 384; i += 128) w1s[i] = w1[i];
    for (int i = tid; i < 192; i += 128) w2s[i] = w2[i];
    if (tid < 64) b1s[tid] = b1[tid];
    if (tid < 3)  b2s[tid] = b2[tid];

    float s = sp[0];
    float dv = g_dbuf[0][r * MAXS + tid];
    dsh[tid] = dv;
    cdfsh[tid] = sigmoid_precise(g_sbuf[0][r * MAXS + tid] * s);
    __syncthreads();

    float a = 0.0f;
    if (tid < 127)
        a = fmaxf((cdfsh[tid] - cdfsh[tid + 1]) / (cdfsh[tid] + 1e-10f), 0.0f);
    alphash[tid] = a;
    __syncthreads();
    scan[tid] = (tid == 0) ? 1.0f : (1.0f - alphash[tid - 1] + 1e-10f);
    __syncthreads();
#pragma unroll
    for (int off = 1; off < 128; off <<= 1) {
        float t = (tid >= off) ? scan[tid - off] : 1.0f;
        __syncthreads();
        scan[tid] *= t;
        __syncthreads();
    }

    float rr = 0.f, gg = 0.f, bb = 0.f;
    if (tid < 127) {
        float vw = alphash[tid] * scan[tid];
        float dm = 0.5f * (dsh[tid] + dsh[tid + 1]);
        float ox = o[r * 3 + 0], oy = o[r * 3 + 1], oz = o[r * 3 + 2];
        float dx = g_dirs[r * 3 + 0], dy = g_dirs[r * 3 + 1], dz = g_dirs[r * 3 + 2];
        float x0 = fmaf(dm, dx, ox), x1 = fmaf(dm, dy, oy), x2 = fmaf(dm, dz, oz);
        float a0 = b2s[0], a1 = b2s[1], a2 = b2s[2];
#pragma unroll 8
        for (int j = 0; j < 64; j++) {
            float h = b1s[j];
            h = fmaf(x0, w1s[j], h);
            h = fmaf(x1, w1s[64 + j], h);
            h = fmaf(x2, w1s[128 + j], h);
            h = fmaf(dx, w1s[192 + j], h);
            h = fmaf(dy, w1s[256 + j], h);
            h = fmaf(dz, w1s[320 + j], h);
            h = softplus_fast(h);
            a0 = fmaf(h, w2s[j * 3 + 0], a0);
            a1 = fmaf(h, w2s[j * 3 + 1], a1);
            a2 = fmaf(h, w2s[j * 3 + 2], a2);
        }
        rr = sigmoid_fast(a0) * vw;
        gg = sigmoid_fast(a1) * vw;
        bb = sigmoid_fast(a2) * vw;
    }
    red0[tid] = rr; red1[tid] = gg; red2[tid] = bb;
    __syncthreads();
    for (int off = 64; off > 0; off >>= 1) {
        if (tid < off) {
            red0[tid] += red0[tid + off];
            red1[tid] += red1[tid + off];
            red2[tid] += red2[tid + off];
        }
        __syncthreads();
    }
    if (tid < 3) {
        float v = (tid == 0) ? red0[0] : (tid == 1) ? red1[0] : red2[0];
        out[r * 3 + tid] = v;
    }
}

// ---------------- launch ----------------------------------------------------
extern "C" void kernel_launch(void* const* d_in, const int* in_sizes, int n_in,
                              void* d_out, int out_size) {
    const float* rays_o = (const float*)d_in[0];
    const float* rays_d = (const float*)d_in[1];
    const float* nearp  = (const float*)d_in[2];
    const float* farp   = (const float*)d_in[3];
    const float* s_ptr  = (const float*)d_in[4];
    const float* sw1 = (const float*)d_in[5];
    const float* sb1 = (const float*)d_in[6];
    const float* sw2 = (const float*)d_in[7];
    const float* sb2 = (const float*)d_in[8];
    const float* sw3 = (const float*)d_in[9];
    const float* sb3 = (const float*)d_in[10];
    const float* rw1 = (const float*)d_in[11];
    const float* rb1 = (const float*)d_in[12];
    const float* rw2 = (const float*)d_in[13];
    const float* rb2 = (const float*)d_in[14];
    float* out = (float*)d_out;

    init_kernel<<<(NRAYS + 255) / 256, 256>>>(rays_d, nearp, farp);

    int npts_coarse = NRAYS * 64;
    int thr_coarse = npts_coarse / 2;
    sdf_kernel<<<(thr_coarse + 255) / 256, 256>>>(
        rays_o, sw1, sb1, sw2, sb2, sw3, sb3, 0, npts_coarse);

    int npts_fine = NRAYS * 16;
    int thr_fine = npts_fine / 2;
    int warps_grid = (NRAYS * 32 + 255) / 256;   // one warp per ray
    int pp = 0;
    for (int i = 0; i < 4; i++) {
        int n = 64 + 16 * i;
        float si = 64.0f * (float)(1 << i);
        upsample_kernel<<<warps_grid, 256>>>(n, si, pp);
        sdf_kernel<<<(thr_fine + 255) / 256, 256>>>(
            rays_o, sw1, sb1, sw2, sb2, sw3, sb3, 1, npts_fine);
        merge_kernel<<<warps_grid, 256>>>(n, pp);
        pp ^= 1;
    }
    // after 4 flips pp == 0: final data in buffer 0
    render_kernel<<<NRAYS, 128>>>(rays_o, s_ptr, rw1, rb1, rw2, rb2, out);
}

// round 7
// speedup vs baseline: 1.1381x; 1.1381x over previous
#include <cuda_runtime.h>
#include <math.h>

#define NRAYS 16384
#define MAXS 128

typedef unsigned long long u64;

// ---------------- scratch (device globals; no allocation allowed) ----------
__device__ float g_dirs[NRAYS * 3];
__device__ float g_dbuf[2][NRAYS * MAXS];
__device__ float g_sbuf[2][NRAYS * MAXS];
__device__ float g_dfine[NRAYS * 16];
__device__ float g_sdff[NRAYS * 16];

// ---------------- math helpers ---------------------------------------------
__device__ __forceinline__ float softplus_fast(float x) {
    float t = __expf(-fabsf(x));
    return fmaxf(x, 0.0f) + __logf(1.0f + t);
}
__device__ __forceinline__ float sigmoid_fast(float x) {
    return __fdividef(1.0f, 1.0f + __expf(-x));
}
__device__ __forceinline__ float sigmoid_precise(float x) {
    return 1.0f / (1.0f + expf(-x));
}

// ---------------- packed f32x2 helpers (Blackwell FFMA2) --------------------
__device__ __forceinline__ u64 pack2(float lo, float hi) {
    u64 r;
    asm("mov.b64 %0, {%1, %2};" : "=l"(r) : "f"(lo), "f"(hi));
    return r;
}
__device__ __forceinline__ void unpack2(u64 v, float& lo, float& hi) {
    asm("mov.b64 {%0, %1}, %2;" : "=f"(lo), "=f"(hi) : "l"(v));
}
__device__ __forceinline__ u64 ffma2(u64 a, u64 b, u64 c) {
    u64 d;
    asm("fma.rn.f32x2 %0, %1, %2, %3;" : "=l"(d) : "l"(a), "l"(b), "l"(c));
    return d;
}

// ---------------- init: normalize dirs, fill coarse d ----------------------
__global__ void init_kernel(const float* __restrict__ rd,
                            const float* __restrict__ nearp,
                            const float* __restrict__ farp) {
    int r = blockIdx.x * blockDim.x + threadIdx.x;
    if (r >= NRAYS) return;
    float dx = rd[r * 3 + 0], dy = rd[r * 3 + 1], dz = rd[r * 3 + 2];
    float nrm = sqrtf(dx * dx + dy * dy + dz * dz);
    dx /= nrm; dy /= nrm; dz /= nrm;
    g_dirs[r * 3 + 0] = dx; g_dirs[r * 3 + 1] = dy; g_dirs[r * 3 + 2] = dz;
    float nr = nearp[r], fr = farp[r];
    for (int j = 0; j < 64; j++) {
        float t = (float)j / 63.0f;
        g_dbuf[0][r * MAXS + j] = nr * (1.0f - t) + fr * t;
    }
}

// ---------------- SDF MLP: block-GEMM, 64 points per CTA --------------------
// mode 0: coarse (g_dbuf[0], stride 128, 64/ray -> g_sbuf[0])
// mode 1: fine   (g_dfine, stride 16, 16/ray -> g_sdff)
__global__ void __launch_bounds__(256)
sdf_kernel(const float* __restrict__ o,
           const float* __restrict__ w1, const float* __restrict__ b1,
           const float* __restrict__ w2, const float* __restrict__ b2,
           const float* __restrict__ w3, const float* __restrict__ b3,
           int mode) {
    __shared__ __align__(16) float w2s[64 * 64];   // [k][q] (input layout)
    __shared__ __align__(16) float hsh[64 * 64];   // [k][pt]
    __shared__ float w1s[192], b1s[64], b2s[64], w3s[64];
    __shared__ float pnorm[64];
    __shared__ float partial[8 * 64];               // [qg][pt]
    __shared__ float b3s;

    int tid = threadIdx.x;
    for (int i = tid; i < 4096; i += 256) w2s[i] = w2[i];
    if (tid < 192) w1s[tid] = w1[tid];
    if (tid < 64) { b1s[tid] = b1[tid]; b2s[tid] = b2[tid]; w3s[tid] = w3[tid]; }
    if (tid == 0) b3s = b3[0];
    __syncthreads();

    const float* dvals = mode ? g_dfine : g_dbuf[0];
    float* outp        = mode ? g_sdff  : g_sbuf[0];
    int spr    = mode ? 16 : 64;
    int stride = mode ? 16 : MAXS;

    // ---- layer 1: 256 threads = 64 pts x 4 k-groups of 16 ----
    {
        int pt = tid & 63, kg = tid >> 6;
        int gp = blockIdx.x * 64 + pt;
        int ray = gp / spr;
        int j   = gp - ray * spr;
        float dv = dvals[ray * stride + j];
        float ox = o[ray * 3 + 0], oy = o[ray * 3 + 1], oz = o[ray * 3 + 2];
        float dx = g_dirs[ray * 3 + 0], dy = g_dirs[ray * 3 + 1], dz = g_dirs[ray * 3 + 2];
        float px = fmaf(dv, dx, ox), py = fmaf(dv, dy, oy), pz = fmaf(dv, dz, oz);
        if (kg == 0)
            pnorm[pt] = sqrtf(fmaf(px, px, fmaf(py, py, pz * pz)));
        int k0 = kg * 16;
#pragma unroll
        for (int k = k0; k < k0 + 16; k++) {
            float a = b1s[k];
            a = fmaf(px, w1s[k], a);
            a = fmaf(py, w1s[64 + k], a);
            a = fmaf(pz, w1s[128 + k], a);
            hsh[k * 64 + pt] = softplus_fast(a);
        }
    }
    __syncthreads();

    // ---- layer 2: 256 threads = 32 pt-pairs x 8 q-groups of 8 ----
    {
        int pp = tid & 31;          // point pair: pts 2pp, 2pp+1
        int qg = tid >> 5;          // q group: q0 = qg*8 (warp-uniform!)
        int q0 = qg * 8;

        u64 acca[4] = {0, 0, 0, 0};
        u64 accb[4] = {0, 0, 0, 0};
#pragma unroll 8
        for (int k = 0; k < 64; k++) {
            float2 hab = *(const float2*)&hsh[k * 64 + 2 * pp];
            u64 hda = pack2(hab.x, hab.x);
            u64 hdb = pack2(hab.y, hab.y);
            const ulonglong2* wr = (const ulonglong2*)&w2s[k * 64 + q0];
            ulonglong2 wA = wr[0];   // (w[q0],w[q0+1]) , (w[q0+2],w[q0+3])
            ulonglong2 wB = wr[1];   // (w[q0+4],...)
            acca[0] = ffma2(hda, wA.x, acca[0]);
            acca[1] = ffma2(hda, wA.y, acca[1]);
            acca[2] = ffma2(hda, wB.x, acca[2]);
            acca[3] = ffma2(hda, wB.y, acca[3]);
            accb[0] = ffma2(hdb, wA.x, accb[0]);
            accb[1] = ffma2(hdb, wA.y, accb[1]);
            accb[2] = ffma2(hdb, wB.x, accb[2]);
            accb[3] = ffma2(hdb, wB.y, accb[3]);
        }
        // epilogue: softplus + layer3 partials over my 8 q's
        float pa = 0.0f, pb = 0.0f;
#pragma unroll
        for (int jj = 0; jj < 4; jj++) {
            int q = q0 + 2 * jj;
            float lo, hi;
            unpack2(acca[jj], lo, hi);
            pa = fmaf(softplus_fast(lo + b2s[q]),     w3s[q],     pa);
            pa = fmaf(softplus_fast(hi + b2s[q + 1]), w3s[q + 1], pa);
            unpack2(accb[jj], lo, hi);
            pb = fmaf(softplus_fast(lo + b2s[q]),     w3s[q],     pb);
            pb = fmaf(softplus_fast(hi + b2s[q + 1]), w3s[q + 1], pb);
        }
        partial[qg * 64 + 2 * pp]     = pa;
        partial[qg * 64 + 2 * pp + 1] = pb;
    }
    __syncthreads();

    // ---- final reduce + write: 64 threads, one per point ----
    if (tid < 64) {
        float s = 0.0f;
#pragma unroll
        for (int g = 0; g < 8; g++) s += partial[g * 64 + tid];
        int gp = blockIdx.x * 64 + tid;
        int ray = gp / spr;
        int j   = gp - ray * spr;
        outp[ray * stride + j] = pnorm[tid] - 0.8f + 0.1f * (b3s + s);
    }
}

// ---------------- upsample: one warp per ray --------------------------------
#define UP_PAD 116
__global__ void upsample_kernel(int n, float s_i, int pp) {
    int gwarp = (blockIdx.x * blockDim.x + threadIdx.x) >> 5;
    int lane  = threadIdx.x & 31;
    int wib   = (threadIdx.x >> 5);
    __shared__ float scdf[8 * UP_PAD];
    if (gwarp >= NRAYS) return;

    const float* d  = g_dbuf[pp] + gwarp * MAXS;
    const float* sd = g_sbuf[pp] + gwarp * MAXS;
    int m = n - 1;
    int base = lane * 4;

    float dj[5], sj[5];
#pragma unroll
    for (int i = 0; i < 5; i++) {
        int idx = base + i;
        bool v = idx < n;
        dj[i] = v ? d[idx] : 1.0f;
        sj[i] = v ? sd[idx] : 0.0f;
    }

    float raw[4];
#pragma unroll
    for (int i = 0; i < 4; i++)
        raw[i] = (sj[i + 1] - sj[i]) / (dj[i + 1] - dj[i] + 1e-5f);

    float prevr = __shfl_up_sync(0xffffffffu, raw[3], 1);
    if (lane == 0) prevr = 0.0f;

    float alpha[4];
#pragma unroll
    for (int i = 0; i < 4; i++) {
        float dvv = fminf(prevr, raw[i]);
        prevr = raw[i];
        dvv = fminf(fmaxf(dvv, -10.0f), 0.0f);
        float mid  = 0.5f * (sj[i] + sj[i + 1]);
        float dist = dj[i + 1] - dj[i];
        float pe = mid - dvv * dist * 0.5f;
        float ne = mid + dvv * dist * 0.5f;
        float pc = sigmoid_precise(pe * s_i);
        float nc = sigmoid_precise(ne * s_i);
        alpha[i] = (pc - nc + 1e-5f) / (pc + 1e-5f);
    }

    float Tloc[4], pl = 1.0f;
#pragma unroll
    for (int i = 0; i < 4; i++) {
        Tloc[i] = pl;
        float om = (base + i < m) ? (1.0f - alpha[i] + 1e-10f) : 1.0f;
        pl *= om;
    }
    float v = pl;
#pragma unroll
    for (int off = 1; off < 32; off <<= 1) {
        float t = __shfl_up_sync(0xffffffffu, v, off);
        if (lane >= off) v *= t;
    }
    float exp_ = __shfl_up_sync(0xffffffffu, v, 1);
    if (lane == 0) exp_ = 1.0f;

    float wp[4], sl = 0.0f, sloc[4];
#pragma unroll
    for (int i = 0; i < 4; i++) {
        float T = exp_ * Tloc[i];
        wp[i] = (base + i < m) ? fmaf(alpha[i], T, 1e-5f) : 0.0f;
        sl += wp[i];
        sloc[i] = sl;
    }
    float tot = sl;
#pragma unroll
    for (int off = 16; off > 0; off >>= 1)
        tot += __shfl_xor_sync(0xffffffffu, tot, off);
    float vs = sl;
#pragma unroll
    for (int off = 1; off < 32; off <<= 1) {
        float t = __shfl_up_sync(0xffffffffu, vs, off);
        if (lane >= off) vs += t;
    }
    float exs = __shfl_up_sync(0xffffffffu, vs, 1);
    if (lane == 0) exs = 0.0f;

    float inv = 1.0f / tot;
    float* cdf = scdf + wib * UP_PAD;
    if (lane == 0) cdf[0] = 0.0f;
#pragma unroll
    for (int i = 0; i < 4; i++) {
        int j = base + i;
        if (j < m) cdf[j + 1] = (exs + sloc[i]) * inv;
    }
    __syncwarp();

    if (lane < 16) {
        float u = (float)lane / 15.0f;
        int lo = 0, hi = n;
        while (lo < hi) {
            int mm = (lo + hi) >> 1;
            if (cdf[mm] <= u) lo = mm + 1; else hi = mm;
        }
        int below = lo - 1;
        if (below < 0) below = 0;
        if (below > n - 1) below = n - 1;
        int above = lo;
        if (above > n - 1) above = n - 1;
        float cb = cdf[below], ca = cdf[above];
        float bb = d[below],   ba = d[above];
        float den = ca - cb;
        if (den < 1e-5f) den = 1.0f;
        float t = (u - cb) / den;
        g_dfine[gwarp * 16 + lane] = bb + t * (ba - bb);
    }
}

// ---------------- parallel stable merge (rank & scatter), ping-pong ---------
__global__ void merge_kernel(int n, int pp) {
    int gwarp = (blockIdx.x * blockDim.x + threadIdx.x) >> 5;
    int lane  = threadIdx.x & 31;
    if (gwarp >= NRAYS) return;
    const float* d  = g_dbuf[pp] + gwarp * MAXS;
    const float* sd = g_sbuf[pp] + gwarp * MAXS;
    float* dd = g_dbuf[pp ^ 1] + gwarp * MAXS;
    float* ds = g_sbuf[pp ^ 1] + gwarp * MAXS;
    const float* fd = g_dfine + gwarp * 16;
    const float* fs = g_sdff  + gwarp * 16;

    if (lane < 16) {
        float v = fd[lane];
        int lo = 0, hi = n;                // count old <= v
        while (lo < hi) { int mm = (lo + hi) >> 1; if (d[mm] <= v) lo = mm + 1; else hi = mm; }
        dd[lo + lane] = v;
        ds[lo + lane] = fs[lane];
    }
    for (int a = lane; a < n; a += 32) {
        float v = d[a];
        int lo = 0, hi = 16;               // count new < v
        while (lo < hi) { int mm = (lo + hi) >> 1; if (fd[mm] < v) lo = mm + 1; else hi = mm; }
        dd[a + lo] = v;
        ds[a + lo] = sd[a];
    }
}

// ---------------- final render: compositing + radiance MLP ------------------
__global__ void render_kernel(const float* __restrict__ o,
                              const float* __restrict__ sp,
                              const float* __restrict__ w1, const float* __restrict__ b1,
                              const float* __restrict__ w2, const float* __restrict__ b2,
                              float* __restrict__ out) {
    int r = blockIdx.x;
    int tid = threadIdx.x;
    __shared__ float dsh[128], cdfsh[128], alphash[128], scan[128];
    __shared__ float w1s[384], b1s[64], w2s[192], b2s[3];
    __shared__ float red0[128], red1[128], red2[128];

    for (int i = tid; i < 384; i += 128) w1s[i] = w1[i];
    for (int i = tid; i < 192; i += 128) w2s[i] = w2[i];
    if (tid < 64) b1s[tid] = b1[tid];
    if (tid < 3)  b2s[tid] = b2[tid];

    float s = sp[0];
    float dv = g_dbuf[0][r * MAXS + tid];
    dsh[tid] = dv;
    cdfsh[tid] = sigmoid_precise(g_sbuf[0][r * MAXS + tid] * s);
    __syncthreads();

    float a = 0.0f;
    if (tid < 127)
        a = fmaxf((cdfsh[tid] - cdfsh[tid + 1]) / (cdfsh[tid] + 1e-10f), 0.0f);
    alphash[tid] = a;
    __syncthreads();
    scan[tid] = (tid == 0) ? 1.0f : (1.0f - alphash[tid - 1] + 1e-10f);
    __syncthreads();
#pragma unroll
    for (int off = 1; off < 128; off <<= 1) {
        float t = (tid >= off) ? scan[tid - off] : 1.0f;
        __syncthreads();
        scan[tid] *= t;
        __syncthreads();
    }

    float rr = 0.f, gg = 0.f, bb = 0.f;
    if (tid < 127) {
        float vw = alphash[tid] * scan[tid];
        float dm = 0.5f * (dsh[tid] + dsh[tid + 1]);
        float ox = o[r * 3 + 0], oy = o[r * 3 + 1], oz = o[r * 3 + 2];
        float dx = g_dirs[r * 3 + 0], dy = g_dirs[r * 3 + 1], dz = g_dirs[r * 3 + 2];
        float x0 = fmaf(dm, dx, ox), x1 = fmaf(dm, dy, oy), x2 = fmaf(dm, dz, oz);
        float a0 = b2s[0], a1 = b2s[1], a2 = b2s[2];
#pragma unroll 8
        for (int j = 0; j < 64; j++) {
            float h = b1s[j];
            h = fmaf(x0, w1s[j], h);
            h = fmaf(x1, w1s[64 + j], h);
            h = fmaf(x2, w1s[128 + j], h);
            h = fmaf(dx, w1s[192 + j], h);
            h = fmaf(dy, w1s[256 + j], h);
            h = fmaf(dz, w1s[320 + j], h);
            h = softplus_fast(h);
            a0 = fmaf(h, w2s[j * 3 + 0], a0);
            a1 = fmaf(h, w2s[j * 3 + 1], a1);
            a2 = fmaf(h, w2s[j * 3 + 2], a2);
        }
        rr = sigmoid_fast(a0) * vw;
        gg = sigmoid_fast(a1) * vw;
        bb = sigmoid_fast(a2) * vw;
    }
    red0[tid] = rr; red1[tid] = gg; red2[tid] = bb;
    __syncthreads();
    for (int off = 64; off > 0; off >>= 1) {
        if (tid < off) {
            red0[tid] += red0[tid + off];
            red1[tid] += red1[tid + off];
            red2[tid] += red2[tid + off];
        }
        __syncthreads();
    }
    if (tid < 3) {
        float v = (tid == 0) ? red0[0] : (tid == 1) ? red1[0] : red2[0];
        out[r * 3 + tid] = v;
    }
}

// ---------------- launch ----------------------------------------------------
extern "C" void kernel_launch(void* const* d_in, const int* in_sizes, int n_in,
                              void* d_out, int out_size) {
    const float* rays_o = (const float*)d_in[0];
    const float* rays_d = (const float*)d_in[1];
    const float* nearp  = (const float*)d_in[2];
    const float* farp   = (const float*)d_in[3];
    const float* s_ptr  = (const float*)d_in[4];
    const float* sw1 = (const float*)d_in[5];
    const float* sb1 = (const float*)d_in[6];
    const float* sw2 = (const float*)d_in[7];
    const float* sb2 = (const float*)d_in[8];
    const float* sw3 = (const float*)d_in[9];
    const float* sb3 = (const float*)d_in[10];
    const float* rw1 = (const float*)d_in[11];
    const float* rb1 = (const float*)d_in[12];
    const float* rw2 = (const float*)d_in[13];
    const float* rb2 = (const float*)d_in[14];
    float* out = (float*)d_out;

    init_kernel<<<(NRAYS + 255) / 256, 256>>>(rays_d, nearp, farp);

    int cta_coarse = NRAYS * 64 / 64;   // 64 pts per CTA
    sdf_kernel<<<cta_coarse, 256>>>(
        rays_o, sw1, sb1, sw2, sb2, sw3, sb3, 0);

    int cta_fine = NRAYS * 16 / 64;
    int warps_grid = (NRAYS * 32 + 255) / 256;   // one warp per ray
    int pp = 0;
    for (int i = 0; i < 4; i++) {
        int n = 64 + 16 * i;
        float si = 64.0f * (float)(1 << i);
        upsample_kernel<<<warps_grid, 256>>>(n, si, pp);
        sdf_kernel<<<cta_fine, 256>>>(
            rays_o, sw1, sb1, sw2, sb2, sw3, sb3, 1);
        merge_kernel<<<warps_grid, 256>>>(n, pp);
        pp ^= 1;
    }
    // after 4 flips pp == 0: final data in buffer 0
    render_kernel<<<NRAYS, 128>>>(rays_o, s_ptr, rw1, rb1, rw2, rb2, out);
}

// round 8
// speedup vs baseline: 1.2360x; 1.0860x over previous
#include <cuda_runtime.h>
#include <math.h>

#define NRAYS 16384
#define MAXS 128

typedef unsigned long long u64;

// ---------------- scratch (device globals; no allocation allowed) ----------
__device__ float g_dirs[NRAYS * 3];
__device__ float g_dbuf[2][NRAYS * MAXS];
__device__ float g_sbuf[2][NRAYS * MAXS];
__device__ float g_dfine[NRAYS * 16];
__device__ float g_sdff[NRAYS * 16];

// ---------------- math helpers ---------------------------------------------
__device__ __forceinline__ float softplus_fast(float x) {
    float t = __expf(-fabsf(x));
    return fmaxf(x, 0.0f) + __logf(1.0f + t);
}
__device__ __forceinline__ float sigmoid_fast(float x) {
    return __fdividef(1.0f, 1.0f + __expf(-x));
}
__device__ __forceinline__ float sigmoid_precise(float x) {
    return 1.0f / (1.0f + expf(-x));
}

// ---------------- packed f32x2 helpers (Blackwell FFMA2) --------------------
__device__ __forceinline__ u64 pack2(float lo, float hi) {
    u64 r;
    asm("mov.b64 %0, {%1, %2};" : "=l"(r) : "f"(lo), "f"(hi));
    return r;
}
__device__ __forceinline__ void unpack2(u64 v, float& lo, float& hi) {
    asm("mov.b64 {%0, %1}, %2;" : "=f"(lo), "=f"(hi) : "l"(v));
}
__device__ __forceinline__ u64 ffma2(u64 a, u64 b, u64 c) {
    u64 d;
    asm("fma.rn.f32x2 %0, %1, %2, %3;" : "=l"(d) : "l"(a), "l"(b), "l"(c));
    return d;
}

// ---------------- init: normalize dirs, fill coarse d ----------------------
__global__ void init_kernel(const float* __restrict__ rd,
                            const float* __restrict__ nearp,
                            const float* __restrict__ farp) {
    int r = blockIdx.x * blockDim.x + threadIdx.x;
    if (r >= NRAYS) return;
    float dx = rd[r * 3 + 0], dy = rd[r * 3 + 1], dz = rd[r * 3 + 2];
    float nrm = sqrtf(dx * dx + dy * dy + dz * dz);
    dx /= nrm; dy /= nrm; dz /= nrm;
    g_dirs[r * 3 + 0] = dx; g_dirs[r * 3 + 1] = dy; g_dirs[r * 3 + 2] = dz;
    float nr = nearp[r], fr = farp[r];
    for (int j = 0; j < 64; j++) {
        float t = (float)j / 63.0f;
        g_dbuf[0][r * MAXS + j] = nr * (1.0f - t) + fr * t;
    }
}

// ---------------- SDF MLP: block-GEMM, 128 points per CTA -------------------
// smem layout (floats):
//   [0,4096)       w2s  [k][q]
//   [4096,12288)   hsh  [k][pt]  pt=128
//   [12288,12800)  partial [qg=4][pt=128]
//   [12800,12992)  w1s
//   [12992,13056)  b1s
//   [13056,13120)  b2s
//   [13120,13184)  w3s
//   [13184,13312)  pnorm
//   [13312]        b3s
#define SDF_SMEM_FLOATS 13320
__global__ void __launch_bounds__(256)
sdf_kernel(const float* __restrict__ o,
           const float* __restrict__ w1, const float* __restrict__ b1,
           const float* __restrict__ w2, const float* __restrict__ b2,
           const float* __restrict__ w3, const float* __restrict__ b3,
           int mode) {
    extern __shared__ __align__(16) float sm[];
    float* w2s    = sm;
    float* hsh    = sm + 4096;
    float* partial= sm + 12288;
    float* w1s    = sm + 12800;
    float* b1s    = sm + 12992;
    float* b2s    = sm + 13056;
    float* w3s    = sm + 13120;
    float* pnorm  = sm + 13184;
    float* b3s    = sm + 13312;

    int tid = threadIdx.x;
    for (int i = tid; i < 4096; i += 256) w2s[i] = w2[i];
    if (tid < 192) w1s[tid] = w1[tid];
    if (tid < 64) { b1s[tid] = b1[tid]; b2s[tid] = b2[tid]; w3s[tid] = w3[tid]; }
    if (tid == 0) b3s[0] = b3[0];
    __syncthreads();

    const float* dvals = mode ? g_dfine : g_dbuf[0];
    float* outp        = mode ? g_sdff  : g_sbuf[0];
    int spr    = mode ? 16 : 64;
    int stride = mode ? 16 : MAXS;

    // ---- layer 1: 256 threads = 128 pts x 2 k-groups of 32 ----
    {
        int pt = tid & 127, kg = tid >> 7;
        int gp = blockIdx.x * 128 + pt;
        int ray = gp / spr;
        int j   = gp - ray * spr;
        float dv = dvals[ray * stride + j];
        float ox = o[ray * 3 + 0], oy = o[ray * 3 + 1], oz = o[ray * 3 + 2];
        float dx = g_dirs[ray * 3 + 0], dy = g_dirs[ray * 3 + 1], dz = g_dirs[ray * 3 + 2];
        float px = fmaf(dv, dx, ox), py = fmaf(dv, dy, oy), pz = fmaf(dv, dz, oz);
        if (kg == 0)
            pnorm[pt] = sqrtf(fmaf(px, px, fmaf(py, py, pz * pz)));
        int k0 = kg * 32;
#pragma unroll
        for (int k = k0; k < k0 + 32; k++) {
            float a = b1s[k];
            a = fmaf(px, w1s[k], a);
            a = fmaf(py, w1s[64 + k], a);
            a = fmaf(pz, w1s[128 + k], a);
            hsh[k * 128 + pt] = softplus_fast(a);
        }
    }
    __syncthreads();

    // ---- layer 2: 256 threads = 64 pt-pairs x 4 q-groups of 16 ----
    {
        int pp = tid & 63;          // point pair: pts 2pp, 2pp+1
        int qg = tid >> 6;          // q group (warp-uniform): q0 = qg*16
        int q0 = qg * 16;

        u64 acca[8] = {0, 0, 0, 0, 0, 0, 0, 0};
        u64 accb[8] = {0, 0, 0, 0, 0, 0, 0, 0};
#pragma unroll 4
        for (int k = 0; k < 64; k++) {
            float2 hab = *(const float2*)&hsh[k * 128 + 2 * pp];
            u64 hda = pack2(hab.x, hab.x);
            u64 hdb = pack2(hab.y, hab.y);
            const ulonglong2* wr = (const ulonglong2*)&w2s[k * 64 + q0];
            ulonglong2 w0 = wr[0];
            ulonglong2 w1v = wr[1];
            ulonglong2 w2v = wr[2];
            ulonglong2 w3v = wr[3];
            acca[0] = ffma2(hda, w0.x,  acca[0]);
            acca[1] = ffma2(hda, w0.y,  acca[1]);
            acca[2] = ffma2(hda, w1v.x, acca[2]);
            acca[3] = ffma2(hda, w1v.y, acca[3]);
            acca[4] = ffma2(hda, w2v.x, acca[4]);
            acca[5] = ffma2(hda, w2v.y, acca[5]);
            acca[6] = ffma2(hda, w3v.x, acca[6]);
            acca[7] = ffma2(hda, w3v.y, acca[7]);
            accb[0] = ffma2(hdb, w0.x,  accb[0]);
            accb[1] = ffma2(hdb, w0.y,  accb[1]);
            accb[2] = ffma2(hdb, w1v.x, accb[2]);
            accb[3] = ffma2(hdb, w1v.y, accb[3]);
            accb[4] = ffma2(hdb, w2v.x, accb[4]);
            accb[5] = ffma2(hdb, w2v.y, accb[5]);
            accb[6] = ffma2(hdb, w3v.x, accb[6]);
            accb[7] = ffma2(hdb, w3v.y, accb[7]);
        }
        // epilogue: softplus + layer3 partials over my 16 q's
        float pa = 0.0f, pb = 0.0f;
#pragma unroll
        for (int jj = 0; jj < 8; jj++) {
            int q = q0 + 2 * jj;
            float lo, hi;
            unpack2(acca[jj], lo, hi);
            pa = fmaf(softplus_fast(lo + b2s[q]),     w3s[q],     pa);
            pa = fmaf(softplus_fast(hi + b2s[q + 1]), w3s[q + 1], pa);
            unpack2(accb[jj], lo, hi);
            pb = fmaf(softplus_fast(lo + b2s[q]),     w3s[q],     pb);
            pb = fmaf(softplus_fast(hi + b2s[q + 1]), w3s[q + 1], pb);
        }
        *(float2*)&partial[qg * 128 + 2 * pp] = make_float2(pa, pb);
    }
    __syncthreads();

    // ---- final reduce + write: 128 threads, one per point ----
    if (tid < 128) {
        float s = partial[tid] + partial[128 + tid] +
                  partial[256 + tid] + partial[384 + tid];
        int gp = blockIdx.x * 128 + tid;
        int ray = gp / spr;
        int j   = gp - ray * spr;
        outp[ray * stride + j] = pnorm[tid] - 0.8f + 0.1f * (b3s[0] + s);
    }
}

// ---------------- upsample: one warp per ray --------------------------------
#define UP_PAD 116
__global__ void upsample_kernel(int n, float s_i, int pp) {
    int gwarp = (blockIdx.x * blockDim.x + threadIdx.x) >> 5;
    int lane  = threadIdx.x & 31;
    int wib   = (threadIdx.x >> 5);
    __shared__ float scdf[8 * UP_PAD];
    if (gwarp >= NRAYS) return;

    const float* d  = g_dbuf[pp] + gwarp * MAXS;
    const float* sd = g_sbuf[pp] + gwarp * MAXS;
    int m = n - 1;
    int base = lane * 4;

    float dj[5], sj[5];
#pragma unroll
    for (int i = 0; i < 5; i++) {
        int idx = base + i;
        bool v = idx < n;
        dj[i] = v ? d[idx] : 1.0f;
        sj[i] = v ? sd[idx] : 0.0f;
    }

    float raw[4];
#pragma unroll
    for (int i = 0; i < 4; i++)
        raw[i] = (sj[i + 1] - sj[i]) / (dj[i + 1] - dj[i] + 1e-5f);

    float prevr = __shfl_up_sync(0xffffffffu, raw[3], 1);
    if (lane == 0) prevr = 0.0f;

    float alpha[4];
#pragma unroll
    for (int i = 0; i < 4; i++) {
        float dvv = fminf(prevr, raw[i]);
        prevr = raw[i];
        dvv = fminf(fmaxf(dvv, -10.0f), 0.0f);
        float mid  = 0.5f * (sj[i] + sj[i + 1]);
        float dist = dj[i + 1] - dj[i];
        float pe = mid - dvv * dist * 0.5f;
        float ne = mid + dvv * dist * 0.5f;
        float pc = sigmoid_precise(pe * s_i);
        float nc = sigmoid_precise(ne * s_i);
        alpha[i] = (pc - nc + 1e-5f) / (pc + 1e-5f);
    }

    float Tloc[4], pl = 1.0f;
#pragma unroll
    for (int i = 0; i < 4; i++) {
        Tloc[i] = pl;
        float om = (base + i < m) ? (1.0f - alpha[i] + 1e-10f) : 1.0f;
        pl *= om;
    }
    float v = pl;
#pragma unroll
    for (int off = 1; off < 32; off <<= 1) {
        float t = __shfl_up_sync(0xffffffffu, v, off);
        if (lane >= off) v *= t;
    }
    float exp_ = __shfl_up_sync(0xffffffffu, v, 1);
    if (lane == 0) exp_ = 1.0f;

    float wp[4], sl = 0.0f, sloc[4];
#pragma unroll
    for (int i = 0; i < 4; i++) {
        float T = exp_ * Tloc[i];
        wp[i] = (base + i < m) ? fmaf(alpha[i], T, 1e-5f) : 0.0f;
        sl += wp[i];
        sloc[i] = sl;
    }
    float tot = sl;
#pragma unroll
    for (int off = 16; off > 0; off >>= 1)
        tot += __shfl_xor_sync(0xffffffffu, tot, off);
    float vs = sl;
#pragma unroll
    for (int off = 1; off < 32; off <<= 1) {
        float t = __shfl_up_sync(0xffffffffu, vs, off);
        if (lane >= off) vs += t;
    }
    float exs = __shfl_up_sync(0xffffffffu, vs, 1);
    if (lane == 0) exs = 0.0f;

    float inv = 1.0f / tot;
    float* cdf = scdf + wib * UP_PAD;
    if (lane == 0) cdf[0] = 0.0f;
#pragma unroll
    for (int i = 0; i < 4; i++) {
        int j = base + i;
        if (j < m) cdf[j + 1] = (exs + sloc[i]) * inv;
    }
    __syncwarp();

    if (lane < 16) {
        float u = (float)lane / 15.0f;
        int lo = 0, hi = n;
        while (lo < hi) {
            int mm = (lo + hi) >> 1;
            if (cdf[mm] <= u) lo = mm + 1; else hi = mm;
        }
        int below = lo - 1;
        if (below < 0) below = 0;
        if (below > n - 1) below = n - 1;
        int above = lo;
        if (above > n - 1) above = n - 1;
        float cb = cdf[below], ca = cdf[above];
        float bb = d[below],   ba = d[above];
        float den = ca - cb;
        if (den < 1e-5f) den = 1.0f;
        float t = (u - cb) / den;
        g_dfine[gwarp * 16 + lane] = bb + t * (ba - bb);
    }
}

// ---------------- parallel stable merge (rank & scatter), ping-pong ---------
__global__ void merge_kernel(int n, int pp) {
    int gwarp = (blockIdx.x * blockDim.x + threadIdx.x) >> 5;
    int lane  = threadIdx.x & 31;
    if (gwarp >= NRAYS) return;
    const float* d  = g_dbuf[pp] + gwarp * MAXS;
    const float* sd = g_sbuf[pp] + gwarp * MAXS;
    float* dd = g_dbuf[pp ^ 1] + gwarp * MAXS;
    float* ds = g_sbuf[pp ^ 1] + gwarp * MAXS;
    const float* fd = g_dfine + gwarp * 16;
    const float* fs = g_sdff  + gwarp * 16;

    if (lane < 16) {
        float v = fd[lane];
        int lo = 0, hi = n;                // count old <= v
        while (lo < hi) { int mm = (lo + hi) >> 1; if (d[mm] <= v) lo = mm + 1; else hi = mm; }
        dd[lo + lane] = v;
        ds[lo + lane] = fs[lane];
    }
    for (int a = lane; a < n; a += 32) {
        float v = d[a];
        int lo = 0, hi = 16;               // count new < v
        while (lo < hi) { int mm = (lo + hi) >> 1; if (fd[mm] < v) lo = mm + 1; else hi = mm; }
        dd[a + lo] = v;
        ds[a + lo] = sd[a];
    }
}

// ---------------- final render: compositing + radiance MLP ------------------
__global__ void render_kernel(const float* __restrict__ o,
                              const float* __restrict__ sp,
                              const float* __restrict__ w1, const float* __restrict__ b1,
                              const float* __restrict__ w2, const float* __restrict__ b2,
                              float* __restrict__ out) {
    int r = blockIdx.x;
    int tid = threadIdx.x;
    __shared__ float dsh[128], cdfsh[128], alphash[128], scan[128];
    __shared__ float w1s[384], b1s[64], w2s[192], b2s[3];
    __shared__ float red0[128], red1[128], red2[128];

    for (int i = tid; i < 384; i += 128) w1s[i] = w1[i];
    for (int i = tid; i < 192; i += 128) w2s[i] = w2[i];
    if (tid < 64) b1s[tid] = b1[tid];
    if (tid < 3)  b2s[tid] = b2[tid];

    float s = sp[0];
    float dv = g_dbuf[0][r * MAXS + tid];
    dsh[tid] = dv;
    cdfsh[tid] = sigmoid_precise(g_sbuf[0][r * MAXS + tid] * s);
    __syncthreads();

    float a = 0.0f;
    if (tid < 127)
        a = fmaxf((cdfsh[tid] - cdfsh[tid + 1]) / (cdfsh[tid] + 1e-10f), 0.0f);
    alphash[tid] = a;
    __syncthreads();
    scan[tid] = (tid == 0) ? 1.0f : (1.0f - alphash[tid - 1] + 1e-10f);
    __syncthreads();
#pragma unroll
    for (int off = 1; off < 128; off <<= 1) {
        float t = (tid >= off) ? scan[tid - off] : 1.0f;
        __syncthreads();
        scan[tid] *= t;
        __syncthreads();
    }

    float rr = 0.f, gg = 0.f, bb = 0.f;
    if (tid < 127) {
        float vw = alphash[tid] * scan[tid];
        float dm = 0.5f * (dsh[tid] + dsh[tid + 1]);
        float ox = o[r * 3 + 0], oy = o[r * 3 + 1], oz = o[r * 3 + 2];
        float dx = g_dirs[r * 3 + 0], dy = g_dirs[r * 3 + 1], dz = g_dirs[r * 3 + 2];
        float x0 = fmaf(dm, dx, ox), x1 = fmaf(dm, dy, oy), x2 = fmaf(dm, dz, oz);
        float a0 = b2s[0], a1 = b2s[1], a2 = b2s[2];
#pragma unroll 8
        for (int j = 0; j < 64; j++) {
            float h = b1s[j];
            h = fmaf(x0, w1s[j], h);
            h = fmaf(x1, w1s[64 + j], h);
            h = fmaf(x2, w1s[128 + j], h);
            h = fmaf(dx, w1s[192 + j], h);
            h = fmaf(dy, w1s[256 + j], h);
            h = fmaf(dz, w1s[320 + j], h);
            h = softplus_fast(h);
            a0 = fmaf(h, w2s[j * 3 + 0], a0);
            a1 = fmaf(h, w2s[j * 3 + 1], a1);
            a2 = fmaf(h, w2s[j * 3 + 2], a2);
        }
        rr = sigmoid_fast(a0) * vw;
        gg = sigmoid_fast(a1) * vw;
        bb = sigmoid_fast(a2) * vw;
    }
    red0[tid] = rr; red1[tid] = gg; red2[tid] = bb;
    __syncthreads();
    for (int off = 64; off > 0; off >>= 1) {
        if (tid < off) {
            red0[tid] += red0[tid + off];
            red1[tid] += red1[tid + off];
            red2[tid] += red2[tid + off];
        }
        __syncthreads();
    }
    if (tid < 3) {
        float v = (tid == 0) ? red0[0] : (tid == 1) ? red1[0] : red2[0];
        out[r * 3 + tid] = v;
    }
}

// ---------------- launch ----------------------------------------------------
extern "C" void kernel_launch(void* const* d_in, const int* in_sizes, int n_in,
                              void* d_out, int out_size) {
    const float* rays_o = (const float*)d_in[0];
    const float* rays_d = (const float*)d_in[1];
    const float* nearp  = (const float*)d_in[2];
    const float* farp   = (const float*)d_in[3];
    const float* s_ptr  = (const float*)d_in[4];
    const float* sw1 = (const float*)d_in[5];
    const float* sb1 = (const float*)d_in[6];
    const float* sw2 = (const float*)d_in[7];
    const float* sb2 = (const float*)d_in[8];
    const float* sw3 = (const float*)d_in[9];
    const float* sb3 = (const float*)d_in[10];
    const float* rw1 = (const float*)d_in[11];
    const float* rb1 = (const float*)d_in[12];
    const float* rw2 = (const float*)d_in[13];
    const float* rb2 = (const float*)d_in[14];
    float* out = (float*)d_out;

    const int sdf_smem = SDF_SMEM_FLOATS * 4;
    cudaFuncSetAttribute(sdf_kernel,
                         cudaFuncAttributeMaxDynamicSharedMemorySize, sdf_smem);

    init_kernel<<<(NRAYS + 255) / 256, 256>>>(rays_d, nearp, farp);

    int cta_coarse = NRAYS * 64 / 128;   // 128 pts per CTA
    sdf_kernel<<<cta_coarse, 256, sdf_smem>>>(
        rays_o, sw1, sb1, sw2, sb2, sw3, sb3, 0);

    int cta_fine = NRAYS * 16 / 128;
    int warps_grid = (NRAYS * 32 + 255) / 256;   // one warp per ray
    int pp = 0;
    for (int i = 0; i < 4; i++) {
        int n = 64 + 16 * i;
        float si = 64.0f * (float)(1 << i);
        upsample_kernel<<<warps_grid, 256>>>(n, si, pp);
        sdf_kernel<<<cta_fine, 256, sdf_smem>>>(
            rays_o, sw1, sb1, sw2, sb2, sw3, sb3, 1);
        merge_kernel<<<warps_grid, 256>>>(n, pp);
        pp ^= 1;
    }
    // after 4 flips pp == 0: final data in buffer 0
    render_kernel<<<NRAYS, 128>>>(rays_o, s_ptr, rw1, rb1, rw2, rb2, out);
}

// round 9
// speedup vs baseline: 1.2467x; 1.0087x over previous
#include <cuda_runtime.h>
#include <math.h>

#define NRAYS 16384
#define MAXS 128

typedef unsigned long long u64;

// ---------------- scratch (device globals; no allocation allowed) ----------
__device__ float g_dirs[NRAYS * 3];
__device__ float g_dbuf[2][NRAYS * MAXS];
__device__ float g_sbuf[2][NRAYS * MAXS];
__device__ float g_dfine[NRAYS * 16];
__device__ float g_sdff[NRAYS * 16];

// ---------------- math helpers ---------------------------------------------
__device__ __forceinline__ float softplus_fast(float x) {
    float t = __expf(-fabsf(x));
    return fmaxf(x, 0.0f) + __logf(1.0f + t);
}
__device__ __forceinline__ float sigmoid_fast(float x) {
    return __fdividef(1.0f, 1.0f + __expf(-x));
}
__device__ __forceinline__ float sigmoid_precise(float x) {
    return 1.0f / (1.0f + expf(-x));
}

// ---------------- packed f32x2 helpers (Blackwell FFMA2) --------------------
__device__ __forceinline__ u64 pack2(float lo, float hi) {
    u64 r;
    asm("mov.b64 %0, {%1, %2};" : "=l"(r) : "f"(lo), "f"(hi));
    return r;
}
__device__ __forceinline__ void unpack2(u64 v, float& lo, float& hi) {
    asm("mov.b64 {%0, %1}, %2;" : "=f"(lo), "=f"(hi) : "l"(v));
}
__device__ __forceinline__ u64 ffma2(u64 a, u64 b, u64 c) {
    u64 d;
    asm("fma.rn.f32x2 %0, %1, %2, %3;" : "=l"(d) : "l"(a), "l"(b), "l"(c));
    return d;
}

// ---------------- init: normalize dirs, fill coarse d ----------------------
__global__ void init_kernel(const float* __restrict__ rd,
                            const float* __restrict__ nearp,
                            const float* __restrict__ farp) {
    int r = blockIdx.x * blockDim.x + threadIdx.x;
    if (r >= NRAYS) return;
    float dx = rd[r * 3 + 0], dy = rd[r * 3 + 1], dz = rd[r * 3 + 2];
    float nrm = sqrtf(dx * dx + dy * dy + dz * dz);
    dx /= nrm; dy /= nrm; dz /= nrm;
    g_dirs[r * 3 + 0] = dx; g_dirs[r * 3 + 1] = dy; g_dirs[r * 3 + 2] = dz;
    float nr = nearp[r], fr = farp[r];
    for (int j = 0; j < 64; j++) {
        float t = (float)j / 63.0f;
        g_dbuf[0][r * MAXS + j] = nr * (1.0f - t) + fr * t;
    }
}

// ---------------- SDF MLP: block-GEMM, 128 points per CTA -------------------
// smem layout (floats):
//   [0,4096)       w2s  [k][q]
//   [4096,12288)   hsh  [k][pt]  pt=128
//   [12288,13312)  partial [qg=8][pt=128]
//   [13312,13504)  w1s
//   [13504,13568)  b1s
//   [13568,13632)  b2s
//   [13632,13696)  w3s
//   [13696,13824)  pnorm
//   [13824]        b3s
#define SDF_SMEM_FLOATS 13832
__global__ void __launch_bounds__(256)
sdf_kernel(const float* __restrict__ o,
           const float* __restrict__ w1, const float* __restrict__ b1,
           const float* __restrict__ w2, const float* __restrict__ b2,
           const float* __restrict__ w3, const float* __restrict__ b3,
           int mode) {
    extern __shared__ __align__(16) float sm[];
    float* w2s    = sm;
    float* hsh    = sm + 4096;
    float* partial= sm + 12288;
    float* w1s    = sm + 13312;
    float* b1s    = sm + 13504;
    float* b2s    = sm + 13568;
    float* w3s    = sm + 13632;
    float* pnorm  = sm + 13696;
    float* b3s    = sm + 13824;

    int tid = threadIdx.x;
    for (int i = tid; i < 4096; i += 256) w2s[i] = w2[i];
    if (tid < 192) w1s[tid] = w1[tid];
    if (tid < 64) { b1s[tid] = b1[tid]; b2s[tid] = b2[tid]; w3s[tid] = w3[tid]; }
    if (tid == 0) b3s[0] = b3[0];
    __syncthreads();

    const float* dvals = mode ? g_dfine : g_dbuf[0];
    float* outp        = mode ? g_sdff  : g_sbuf[0];
    int spr    = mode ? 16 : 64;
    int stride = mode ? 16 : MAXS;

    // ---- layer 1: 256 threads = 128 pts x 2 k-groups of 32 ----
    {
        int pt = tid & 127, kg = tid >> 7;
        int gp = blockIdx.x * 128 + pt;
        int ray = gp / spr;
        int j   = gp - ray * spr;
        float dv = dvals[ray * stride + j];
        float ox = o[ray * 3 + 0], oy = o[ray * 3 + 1], oz = o[ray * 3 + 2];
        float dx = g_dirs[ray * 3 + 0], dy = g_dirs[ray * 3 + 1], dz = g_dirs[ray * 3 + 2];
        float px = fmaf(dv, dx, ox), py = fmaf(dv, dy, oy), pz = fmaf(dv, dz, oz);
        if (kg == 0)
            pnorm[pt] = sqrtf(fmaf(px, px, fmaf(py, py, pz * pz)));
        int k0 = kg * 32;
#pragma unroll
        for (int k = k0; k < k0 + 32; k++) {
            float a = b1s[k];
            a = fmaf(px, w1s[k], a);
            a = fmaf(py, w1s[64 + k], a);
            a = fmaf(pz, w1s[128 + k], a);
            hsh[k * 128 + pt] = softplus_fast(a);
        }
    }
    __syncthreads();

    // ---- layer 2: 256 threads = 32 pt-quads x 8 q-groups of 8 ----
    {
        int pq = tid & 31;          // pts 4pq .. 4pq+3
        int qg = tid >> 5;          // q group (warp-uniform): q0 = qg*8
        int q0 = qg * 8;

        u64 acc[4][4];
#pragma unroll
        for (int i = 0; i < 4; i++)
#pragma unroll
            for (int j = 0; j < 4; j++) acc[i][j] = 0;

#pragma unroll 4
        for (int k = 0; k < 64; k++) {
            float4 h4 = *(const float4*)&hsh[k * 128 + 4 * pq];
            const ulonglong2* wr = (const ulonglong2*)&w2s[k * 64 + q0];
            ulonglong2 wA = wr[0];   // q0..q3 (2 packed pairs)
            ulonglong2 wB = wr[1];   // q4..q7
            u64 h0 = pack2(h4.x, h4.x);
            u64 h1 = pack2(h4.y, h4.y);
            u64 h2 = pack2(h4.z, h4.z);
            u64 h3 = pack2(h4.w, h4.w);
            acc[0][0] = ffma2(h0, wA.x, acc[0][0]);
            acc[0][1] = ffma2(h0, wA.y, acc[0][1]);
            acc[0][2] = ffma2(h0, wB.x, acc[0][2]);
            acc[0][3] = ffma2(h0, wB.y, acc[0][3]);
            acc[1][0] = ffma2(h1, wA.x, acc[1][0]);
            acc[1][1] = ffma2(h1, wA.y, acc[1][1]);
            acc[1][2] = ffma2(h1, wB.x, acc[1][2]);
            acc[1][3] = ffma2(h1, wB.y, acc[1][3]);
            acc[2][0] = ffma2(h2, wA.x, acc[2][0]);
            acc[2][1] = ffma2(h2, wA.y, acc[2][1]);
            acc[2][2] = ffma2(h2, wB.x, acc[2][2]);
            acc[2][3] = ffma2(h2, wB.y, acc[2][3]);
            acc[3][0] = ffma2(h3, wA.x, acc[3][0]);
            acc[3][1] = ffma2(h3, wA.y, acc[3][1]);
            acc[3][2] = ffma2(h3, wB.x, acc[3][2]);
            acc[3][3] = ffma2(h3, wB.y, acc[3][3]);
        }

        // epilogue: softplus + layer3 partials over my 8 q's, 4 pts
        float p0 = 0.f, p1 = 0.f, p2 = 0.f, p3 = 0.f;
#pragma unroll
        for (int j = 0; j < 4; j++) {
            int q = q0 + 2 * j;
            float bql = b2s[q], bqh = b2s[q + 1];
            float wql = w3s[q], wqh = w3s[q + 1];
            float lo, hi;
            unpack2(acc[0][j], lo, hi);
            p0 = fmaf(softplus_fast(lo + bql), wql, p0);
            p0 = fmaf(softplus_fast(hi + bqh), wqh, p0);
            unpack2(acc[1][j], lo, hi);
            p1 = fmaf(softplus_fast(lo + bql), wql, p1);
            p1 = fmaf(softplus_fast(hi + bqh), wqh, p1);
            unpack2(acc[2][j], lo, hi);
            p2 = fmaf(softplus_fast(lo + bql), wql, p2);
            p2 = fmaf(softplus_fast(hi + bqh), wqh, p2);
            unpack2(acc[3][j], lo, hi);
            p3 = fmaf(softplus_fast(lo + bql), wql, p3);
            p3 = fmaf(softplus_fast(hi + bqh), wqh, p3);
        }
        *(float4*)&partial[qg * 128 + 4 * pq] = make_float4(p0, p1, p2, p3);
    }
    __syncthreads();

    // ---- final reduce + write: 128 threads, one per point ----
    if (tid < 128) {
        float s = 0.0f;
#pragma unroll
        for (int g = 0; g < 8; g++) s += partial[g * 128 + tid];
        int gp = blockIdx.x * 128 + tid;
        int ray = gp / spr;
        int j   = gp - ray * spr;
        outp[ray * stride + j] = pnorm[tid] - 0.8f + 0.1f * (b3s[0] + s);
    }
}

// ---------------- upsample: one warp per ray --------------------------------
#define UP_PAD 116
__global__ void upsample_kernel(int n, float s_i, int pp) {
    int gwarp = (blockIdx.x * blockDim.x + threadIdx.x) >> 5;
    int lane  = threadIdx.x & 31;
    int wib   = (threadIdx.x >> 5);
    __shared__ float scdf[8 * UP_PAD];
    if (gwarp >= NRAYS) return;

    const float* d  = g_dbuf[pp] + gwarp * MAXS;
    const float* sd = g_sbuf[pp] + gwarp * MAXS;
    int m = n - 1;
    int base = lane * 4;

    float dj[5], sj[5];
#pragma unroll
    for (int i = 0; i < 5; i++) {
        int idx = base + i;
        bool v = idx < n;
        dj[i] = v ? d[idx] : 1.0f;
        sj[i] = v ? sd[idx] : 0.0f;
    }

    float raw[4];
#pragma unroll
    for (int i = 0; i < 4; i++)
        raw[i] = (sj[i + 1] - sj[i]) / (dj[i + 1] - dj[i] + 1e-5f);

    float prevr = __shfl_up_sync(0xffffffffu, raw[3], 1);
    if (lane == 0) prevr = 0.0f;

    float alpha[4];
#pragma unroll
    for (int i = 0; i < 4; i++) {
        float dvv = fminf(prevr, raw[i]);
        prevr = raw[i];
        dvv = fminf(fmaxf(dvv, -10.0f), 0.0f);
        float mid  = 0.5f * (sj[i] + sj[i + 1]);
        float dist = dj[i + 1] - dj[i];
        float pe = mid - dvv * dist * 0.5f;
        float ne = mid + dvv * dist * 0.5f;
        float pc = sigmoid_precise(pe * s_i);
        float nc = sigmoid_precise(ne * s_i);
        alpha[i] = (pc - nc + 1e-5f) / (pc + 1e-5f);
    }

    float Tloc[4], pl = 1.0f;
#pragma unroll
    for (int i = 0; i < 4; i++) {
        Tloc[i] = pl;
        float om = (base + i < m) ? (1.0f - alpha[i] + 1e-10f) : 1.0f;
        pl *= om;
    }
    float v = pl;
#pragma unroll
    for (int off = 1; off < 32; off <<= 1) {
        float t = __shfl_up_sync(0xffffffffu, v, off);
        if (lane >= off) v *= t;
    }
    float exp_ = __shfl_up_sync(0xffffffffu, v, 1);
    if (lane == 0) exp_ = 1.0f;

    float wp[4], sl = 0.0f, sloc[4];
#pragma unroll
    for (int i = 0; i < 4; i++) {
        float T = exp_ * Tloc[i];
        wp[i] = (base + i < m) ? fmaf(alpha[i], T, 1e-5f) : 0.0f;
        sl += wp[i];
        sloc[i] = sl;
    }
    float tot = sl;
#pragma unroll
    for (int off = 16; off > 0; off >>= 1)
        tot += __shfl_xor_sync(0xffffffffu, tot, off);
    float vs = sl;
#pragma unroll
    for (int off = 1; off < 32; off <<= 1) {
        float t = __shfl_up_sync(0xffffffffu, vs, off);
        if (lane >= off) vs += t;
    }
    float exs = __shfl_up_sync(0xffffffffu, vs, 1);
    if (lane == 0) exs = 0.0f;

    float inv = 1.0f / tot;
    float* cdf = scdf + wib * UP_PAD;
    if (lane == 0) cdf[0] = 0.0f;
#pragma unroll
    for (int i = 0; i < 4; i++) {
        int j = base + i;
        if (j < m) cdf[j + 1] = (exs + sloc[i]) * inv;
    }
    __syncwarp();

    if (lane < 16) {
        float u = (float)lane / 15.0f;
        int lo = 0, hi = n;
        while (lo < hi) {
            int mm = (lo + hi) >> 1;
            if (cdf[mm] <= u) lo = mm + 1; else hi = mm;
        }
        int below = lo - 1;
        if (below < 0) below = 0;
        if (below > n - 1) below = n - 1;
        int above = lo;
        if (above > n - 1) above = n - 1;
        float cb = cdf[below], ca = cdf[above];
        float bb = d[below],   ba = d[above];
        float den = ca - cb;
        if (den < 1e-5f) den = 1.0f;
        float t = (u - cb) / den;
        g_dfine[gwarp * 16 + lane] = bb + t * (ba - bb);
    }
}

// ---------------- parallel stable merge (rank & scatter), ping-pong ---------
__global__ void merge_kernel(int n, int pp) {
    int gwarp = (blockIdx.x * blockDim.x + threadIdx.x) >> 5;
    int lane  = threadIdx.x & 31;
    if (gwarp >= NRAYS) return;
    const float* d  = g_dbuf[pp] + gwarp * MAXS;
    const float* sd = g_sbuf[pp] + gwarp * MAXS;
    float* dd = g_dbuf[pp ^ 1] + gwarp * MAXS;
    float* ds = g_sbuf[pp ^ 1] + gwarp * MAXS;
    const float* fd = g_dfine + gwarp * 16;
    const float* fs = g_sdff  + gwarp * 16;

    if (lane < 16) {
        float v = fd[lane];
        int lo = 0, hi = n;                // count old <= v
        while (lo < hi) { int mm = (lo + hi) >> 1; if (d[mm] <= v) lo = mm + 1; else hi = mm; }
        dd[lo + lane] = v;
        ds[lo + lane] = fs[lane];
    }
    for (int a = lane; a < n; a += 32) {
        float v = d[a];
        int lo = 0, hi = 16;               // count new < v
        while (lo < hi) { int mm = (lo + hi) >> 1; if (fd[mm] < v) lo = mm + 1; else hi = mm; }
        dd[a + lo] = v;
        ds[a + lo] = sd[a];
    }
}

// ---------------- final render: compositing + radiance MLP ------------------
__global__ void render_kernel(const float* __restrict__ o,
                              const float* __restrict__ sp,
                              const float* __restrict__ w1, const float* __restrict__ b1,
                              const float* __restrict__ w2, const float* __restrict__ b2,
                              float* __restrict__ out) {
    int r = blockIdx.x;
    int tid = threadIdx.x;
    __shared__ float dsh[128], cdfsh[128], alphash[128], scan[128];
    __shared__ float w1s[384], b1s[64], w2s[192], b2s[3];
    __shared__ float red0[128], red1[128], red2[128];

    for (int i = tid; i < 384; i += 128) w1s[i] = w1[i];
    for (int i = tid; i < 192; i += 128) w2s[i] = w2[i];
    if (tid < 64) b1s[tid] = b1[tid];
    if (tid < 3)  b2s[tid] = b2[tid];

    float s = sp[0];
    float dv = g_dbuf[0][r * MAXS + tid];
    dsh[tid] = dv;
    cdfsh[tid] = sigmoid_precise(g_sbuf[0][r * MAXS + tid] * s);
    __syncthreads();

    float a = 0.0f;
    if (tid < 127)
        a = fmaxf((cdfsh[tid] - cdfsh[tid + 1]) / (cdfsh[tid] + 1e-10f), 0.0f);
    alphash[tid] = a;
    __syncthreads();
    scan[tid] = (tid == 0) ? 1.0f : (1.0f - alphash[tid - 1] + 1e-10f);
    __syncthreads();
#pragma unroll
    for (int off = 1; off < 128; off <<= 1) {
        float t = (tid >= off) ? scan[tid - off] : 1.0f;
        __syncthreads();
        scan[tid] *= t;
        __syncthreads();
    }

    float rr = 0.f, gg = 0.f, bb = 0.f;
    if (tid < 127) {
        float vw = alphash[tid] * scan[tid];
        float dm = 0.5f * (dsh[tid] + dsh[tid + 1]);
        float ox = o[r * 3 + 0], oy = o[r * 3 + 1], oz = o[r * 3 + 2];
        float dx = g_dirs[r * 3 + 0], dy = g_dirs[r * 3 + 1], dz = g_dirs[r * 3 + 2];
        float x0 = fmaf(dm, dx, ox), x1 = fmaf(dm, dy, oy), x2 = fmaf(dm, dz, oz);
        float a0 = b2s[0], a1 = b2s[1], a2 = b2s[2];
#pragma unroll 8
        for (int j = 0; j < 64; j++) {
            float h = b1s[j];
            h = fmaf(x0, w1s[j], h);
            h = fmaf(x1, w1s[64 + j], h);
            h = fmaf(x2, w1s[128 + j], h);
            h = fmaf(dx, w1s[192 + j], h);
            h = fmaf(dy, w1s[256 + j], h);
            h = fmaf(dz, w1s[320 + j], h);
            h = softplus_fast(h);
            a0 = fmaf(h, w2s[j * 3 + 0], a0);
            a1 = fmaf(h, w2s[j * 3 + 1], a1);
            a2 = fmaf(h, w2s[j * 3 + 2], a2);
        }
        rr = sigmoid_fast(a0) * vw;
        gg = sigmoid_fast(a1) * vw;
        bb = sigmoid_fast(a2) * vw;
    }
    red0[tid] = rr; red1[tid] = gg; red2[tid] = bb;
    __syncthreads();
    for (int off = 64; off > 0; off >>= 1) {
        if (tid < off) {
            red0[tid] += red0[tid + off];
            red1[tid] += red1[tid + off];
            red2[tid] += red2[tid + off];
        }
        __syncthreads();
    }
    if (tid < 3) {
        float v = (tid == 0) ? red0[0] : (tid == 1) ? red1[0] : red2[0];
        out[r * 3 + tid] = v;
    }
}

// ---------------- launch ----------------------------------------------------
extern "C" void kernel_launch(void* const* d_in, const int* in_sizes, int n_in,
                              void* d_out, int out_size) {
    const float* rays_o = (const float*)d_in[0];
    const float* rays_d = (const float*)d_in[1];
    const float* nearp  = (const float*)d_in[2];
    const float* farp   = (const float*)d_in[3];
    const float* s_ptr  = (const float*)d_in[4];
    const float* sw1 = (const float*)d_in[5];
    const float* sb1 = (const float*)d_in[6];
    const float* sw2 = (const float*)d_in[7];
    const float* sb2 = (const float*)d_in[8];
    const float* sw3 = (const float*)d_in[9];
    const float* sb3 = (const float*)d_in[10];
    const float* rw1 = (const float*)d_in[11];
    const float* rb1 = (const float*)d_in[12];
    const float* rw2 = (const float*)d_in[13];
    const float* rb2 = (const float*)d_in[14];
    float* out = (float*)d_out;

    const int sdf_smem = SDF_SMEM_FLOATS * 4;
    cudaFuncSetAttribute(sdf_kernel,
                         cudaFuncAttributeMaxDynamicSharedMemorySize, sdf_smem);

    init_kernel<<<(NRAYS + 255) / 256, 256>>>(rays_d, nearp, farp);

    int cta_coarse = NRAYS * 64 / 128;   // 128 pts per CTA
    sdf_kernel<<<cta_coarse, 256, sdf_smem>>>(
        rays_o, sw1, sb1, sw2, sb2, sw3, sb3, 0);

    int cta_fine = NRAYS * 16 / 128;
    int warps_grid = (NRAYS * 32 + 255) / 256;   // one warp per ray
    int pp = 0;
    for (int i = 0; i < 4; i++) {
        int n = 64 + 16 * i;
        float si = 64.0f * (float)(1 << i);
        upsample_kernel<<<warps_grid, 256>>>(n, si, pp);
        sdf_kernel<<<cta_fine, 256, sdf_smem>>>(
            rays_o, sw1, sb1, sw2, sb2, sw3, sb3, 1);
        merge_kernel<<<warps_grid, 256>>>(n, pp);
        pp ^= 1;
    }
    // after 4 flips pp == 0: final data in buffer 0
    render_kernel<<<NRAYS, 128>>>(rays_o, s_ptr, rw1, rb1, rw2, rb2, out);
}